// round 8
// baseline (speedup 1.0000x reference)
#include <cuda_runtime.h>
#include <cuda_fp16.h>
#include <cstdint>

// ============================================================================
// out[m,n] = sum_k x[m,k] * (w[k/128, k%128, n] * scaler[k/128, n])
//   x: [2,1024,4096] f32  (M=2048, K=4096)
//   w: [32,128,4096] INT32 (harness-promoted int8)
//   scaler: [32,4096] f32
//   out: [2048,4096] f32
//
// R7 confirmed SIMT HMMA.F32 roofline rt~12/SMSP (GEMM ~183us invariant).
// R8 experiment: fp16-ACCUMULATOR mma (possible 2x rate), chunked -- fp16
// accumulation over 4 iters (256 k-terms), promoted to fp32. Base shape = R6
// (BM128xBN256, 8 warps, 64x64 warp tiles, 4-stage ring, occ 1).
// ============================================================================

static constexpr int M = 2048;
static constexpr int N = 4096;
static constexpr int K = 4096;

static constexpr int BM = 128;
static constexpr int BN = 256;
static constexpr int BK = 64;            // 64 halves = 128 bytes per row
static constexpr int STAGES = 4;
static constexpr int KITERS = K / BK;    // 64

static constexpr int A_BYTES = BM * BK * 2;              // 16384
static constexpr int B_BYTES = BN * BK * 2;              // 32768
static constexpr int STAGE_BYTES = A_BYTES + B_BYTES;    // 49152
static constexpr int SMEM_TOTAL = STAGES * STAGE_BYTES;  // 196608

// Scratch (static device globals -- allocation-free)
__device__ __half g_x16[(size_t)M * K];   // 16 MB : x fp16, [M][K]
__device__ __half g_wt [(size_t)N * K];   // 32 MB : dequant W^T fp16, [N][K]

// ---------------------------------------------------------------------------
__device__ __forceinline__ uint32_t smem_u32(const void* p) {
    uint32_t a;
    asm("{ .reg .u64 t; cvta.to.shared.u64 t, %1; cvt.u32.u64 %0, t; }"
        : "=r"(a) : "l"(p));
    return a;
}
__device__ __forceinline__ void cp_async_16(uint32_t dst, const void* src) {
    asm volatile("cp.async.cg.shared.global [%0], [%1], 16;"
                 :: "r"(dst), "l"(src) : "memory");
}
__device__ __forceinline__ void cp_commit() {
    asm volatile("cp.async.commit_group;" ::: "memory");
}
__device__ __forceinline__ void cp_wait2() {
    asm volatile("cp.async.wait_group 2;" ::: "memory");
}
__device__ __forceinline__ void ldsm_x4(uint32_t* r, uint32_t addr) {
    asm volatile("ldmatrix.sync.aligned.m8n8.x4.shared.b16 {%0,%1,%2,%3}, [%4];"
                 : "=r"(r[0]), "=r"(r[1]), "=r"(r[2]), "=r"(r[3]) : "r"(addr));
}
// fp16-accumulator HMMA: D(half2 x2) = A*B + D
__device__ __forceinline__ void mma16816_f16(uint32_t* c, const uint32_t* a,
                                             uint32_t b0, uint32_t b1) {
    asm volatile(
        "mma.sync.aligned.m16n8k16.row.col.f16.f16.f16.f16 "
        "{%0,%1}, {%2,%3,%4,%5}, {%6,%7}, {%0,%1};"
        : "+r"(c[0]), "+r"(c[1])
        : "r"(a[0]), "r"(a[1]), "r"(a[2]), "r"(a[3]), "r"(b0), "r"(b1));
}

// ============================================================================
// Kernel 1: x fp32 -> fp16 (8 floats / thread)  [verified]
// ============================================================================
__global__ void __launch_bounds__(256) convert_x_kernel(const float4* __restrict__ x,
                                                        uint4* __restrict__ xo) {
    size_t i = (size_t)blockIdx.x * 256 + threadIdx.x;
    float4 a = x[2 * i];
    float4 b = x[2 * i + 1];
    __half2 h0 = __floats2half2_rn(a.x, a.y);
    __half2 h1 = __floats2half2_rn(a.z, a.w);
    __half2 h2 = __floats2half2_rn(b.x, b.y);
    __half2 h3 = __floats2half2_rn(b.z, b.w);
    uint4 v;
    v.x = reinterpret_cast<uint32_t&>(h0);
    v.y = reinterpret_cast<uint32_t&>(h1);
    v.z = reinterpret_cast<uint32_t&>(h2);
    v.w = reinterpret_cast<uint32_t&>(h3);
    xo[i] = v;
}

// ============================================================================
// Kernel 2: dequant + transpose W -> Wt[n][k] fp16  [verified, int32 input]
// ============================================================================
__global__ void __launch_bounds__(256) dequant_kernel(const int* __restrict__ w,
                                                      const float* __restrict__ sc,
                                                      __half* __restrict__ wt) {
    __shared__ __half tile[128][130];
    const int s  = blockIdx.x;
    const int n0 = blockIdx.y * 128;
    const int tid = threadIdx.x;

    #pragma unroll
    for (int i = tid; i < 128 * 32; i += 256) {
        int c = i >> 5;
        int n = (i & 31) * 4;
        const int4   q = *(const int4*)(w + ((size_t)(s * 128 + c)) * 4096 + n0 + n);
        const float4 f = *(const float4*)(sc + (size_t)s * 4096 + n0 + n);
        __half2 h0 = __floats2half2_rn((float)q.x * f.x, (float)q.y * f.y);
        __half2 h1 = __floats2half2_rn((float)q.z * f.z, (float)q.w * f.w);
        *(__half2*)&tile[c][n]     = h0;
        *(__half2*)&tile[c][n + 2] = h1;
    }
    __syncthreads();

    #pragma unroll
    for (int i = tid; i < 128 * 32; i += 256) {
        int cq = i & 31;
        int n  = i >> 5;
        int c0 = cq * 4;
        uint32_t lo = (uint32_t)__half_as_ushort(tile[c0 + 0][n]) |
                      ((uint32_t)__half_as_ushort(tile[c0 + 1][n]) << 16);
        uint32_t hi = (uint32_t)__half_as_ushort(tile[c0 + 2][n]) |
                      ((uint32_t)__half_as_ushort(tile[c0 + 3][n]) << 16);
        uint2 v; v.x = lo; v.y = hi;
        *(uint2*)(wt + (size_t)(n0 + n) * 4096 + s * 128 + c0) = v;
    }
}

// ============================================================================
// Kernel 3: fp16 HMMA GEMM with fp16 accumulators + chunked fp32 promotion
//   BM=128 x BN=256 x BK=64, 256 threads (8 warps: 2m x 4n, warp 64m x 64n),
//   4-stage cp.async ring, one __syncthreads per iter.
// ============================================================================
__global__ void __launch_bounds__(256, 1)
gemm_kernel(const __half* __restrict__ A, const __half* __restrict__ B,
            float* __restrict__ out) {
    extern __shared__ char smem[];
    const uint32_t sb = smem_u32(smem);

    const int tid  = threadIdx.x;
    const int wid  = tid >> 5;
    const int lane = tid & 31;

    const int mt = blockIdx.x & 15;
    const int nt = blockIdx.x >> 4;
    const int m0 = mt * BM;
    const int n0 = nt * BN;

    const int wm = (wid & 1) * 64;       // 2 warps over m
    const int wn = (wid >> 1) * 64;      // 4 warps over n

    // ---- cp.async bases ----
    const int row0 = tid >> 3;           // 0..31
    const int cc   = tid & 7;
    const uint32_t dst0 = (uint32_t)row0 * 128 + (((cc ^ (row0 & 7)) << 4));
    const __half* a_base = A + (size_t)(m0 + row0) * K + cc * 8;
    const __half* b_base = B + (size_t)(n0 + row0) * K + cc * 8;

    // ---- ldmatrix lane addressing (verified mapping) ----
    int a_row[4];
    #pragma unroll
    for (int mi = 0; mi < 4; ++mi) a_row[mi] = wm + mi * 16 + (lane & 15);
    const int a_hi = lane >> 4;
    const int b_hi = (lane >> 3) & 1;
    int b_row[4];
    #pragma unroll
    for (int nb = 0; nb < 4; ++nb)
        b_row[nb] = wn + nb * 16 + (lane & 7) + 8 * (lane >> 4);

    // fp32 master accumulators + fp16 chunk accumulators
    float accf[4][8][4];
    #pragma unroll
    for (int mi = 0; mi < 4; ++mi)
        #pragma unroll
        for (int ni = 0; ni < 8; ++ni)
            #pragma unroll
            for (int j = 0; j < 4; ++j) accf[mi][ni][j] = 0.f;

    uint32_t acch[4][8][2];
    #pragma unroll
    for (int mi = 0; mi < 4; ++mi)
        #pragma unroll
        for (int ni = 0; ni < 8; ++ni) { acch[mi][ni][0] = 0u; acch[mi][ni][1] = 0u; }

    auto load_stage = [&](int it, int stage) {
        uint32_t sd = sb + stage * STAGE_BYTES;
        size_t koff = (size_t)it * BK;
        #pragma unroll
        for (int i = 0; i < 4; ++i)
            cp_async_16(sd + dst0 + i * (32 * 128), a_base + koff + (size_t)(32 * i) * K);
        #pragma unroll
        for (int i = 0; i < 8; ++i)
            cp_async_16(sd + A_BYTES + dst0 + i * (32 * 128),
                        b_base + koff + (size_t)(32 * i) * K);
    };

    load_stage(0, 0); cp_commit();
    load_stage(1, 1); cp_commit();
    load_stage(2, 2); cp_commit();

    #pragma unroll 1
    for (int it = 0; it < KITERS; ++it) {
        cp_wait2();
        __syncthreads();

        if (it + 3 < KITERS) load_stage(it + 3, (it + 3) & 3);
        cp_commit();

        const uint32_t sA = sb + (it & 3) * STAGE_BYTES;
        const uint32_t sB = sA + A_BYTES;

        #pragma unroll
        for (int ks = 0; ks < 4; ++ks) {
            uint32_t a_frag[4][4], b_frag[4][4];
            #pragma unroll
            for (int mi = 0; mi < 4; ++mi) {
                uint32_t c = (uint32_t)((ks * 2 + a_hi) ^ (a_row[mi] & 7)) << 4;
                ldsm_x4(a_frag[mi], sA + a_row[mi] * 128 + c);
            }
            #pragma unroll
            for (int nb = 0; nb < 4; ++nb) {
                uint32_t c = (uint32_t)((ks * 2 + b_hi) ^ (b_row[nb] & 7)) << 4;
                ldsm_x4(b_frag[nb], sB + b_row[nb] * 128 + c);
            }
            #pragma unroll
            for (int mi = 0; mi < 4; ++mi)
                #pragma unroll
                for (int nb = 0; nb < 4; ++nb) {
                    mma16816_f16(acch[mi][2 * nb + 0], a_frag[mi], b_frag[nb][0], b_frag[nb][1]);
                    mma16816_f16(acch[mi][2 * nb + 1], a_frag[mi], b_frag[nb][2], b_frag[nb][3]);
                }
        }

        // ---- chunk boundary: promote fp16 partials into fp32, reset ----
        if ((it & 3) == 3) {
            #pragma unroll
            for (int mi = 0; mi < 4; ++mi)
                #pragma unroll
                for (int ni = 0; ni < 8; ++ni) {
                    float2 p0 = __half22float2(*reinterpret_cast<__half2*>(&acch[mi][ni][0]));
                    float2 p1 = __half22float2(*reinterpret_cast<__half2*>(&acch[mi][ni][1]));
                    accf[mi][ni][0] += p0.x;
                    accf[mi][ni][1] += p0.y;
                    accf[mi][ni][2] += p1.x;
                    accf[mi][ni][3] += p1.y;
                    acch[mi][ni][0] = 0u;
                    acch[mi][ni][1] = 0u;
                }
        }
    }

    // ---- epilogue (same per-mma c-fragment mapping; KITERS%4==0 so acch empty) ----
    const int r0 = m0 + wm + (lane >> 2);
    const int c0 = n0 + wn + (lane & 3) * 2;
    #pragma unroll
    for (int mi = 0; mi < 4; ++mi) {
        #pragma unroll
        for (int ni = 0; ni < 8; ++ni) {
            int r = r0 + mi * 16;
            int c = c0 + ni * 8;
            *(float2*)(out + (size_t)r * N + c)       = make_float2(accf[mi][ni][0], accf[mi][ni][1]);
            *(float2*)(out + (size_t)(r + 8) * N + c) = make_float2(accf[mi][ni][2], accf[mi][ni][3]);
        }
    }
}

// ============================================================================
// Host launch
// ============================================================================
extern "C" void kernel_launch(void* const* d_in, const int* in_sizes, int n_in,
                              void* d_out, int out_size) {
    const float* x  = (const float*)d_in[0];
    const int*   w  = (const int*)d_in[1];     // int8 promoted to int32 by harness
    const float* sc = (const float*)d_in[2];
    float* out = (float*)d_out;

    void* p_x16 = nullptr;
    void* p_wt  = nullptr;
    cudaGetSymbolAddress(&p_x16, g_x16);
    cudaGetSymbolAddress(&p_wt,  g_wt);

    convert_x_kernel<<<(M * K) / (256 * 8), 256>>>((const float4*)x, (uint4*)p_x16);
    dequant_kernel<<<dim3(32, 32), 256>>>(w, sc, (__half*)p_wt);

    cudaFuncSetAttribute(gemm_kernel, cudaFuncAttributeMaxDynamicSharedMemorySize,
                         SMEM_TOTAL);
    gemm_kernel<<<(M / BM) * (N / BN), 256, SMEM_TOTAL>>>(
        (const __half*)p_x16, (const __half*)p_wt, out);
}

// round 9
// speedup vs baseline: 1.1185x; 1.1185x over previous
#include <cuda_runtime.h>
#include <cuda_fp16.h>
#include <cstdint>

// ============================================================================
// out[m,n] = sum_k x[m,k] * (w[k/128, k%128, n] * scaler[k/128, n])
//   x: [2,1024,4096] f32  (M=2048, K=4096)
//   w: [32,128,4096] INT32 (harness-promoted int8)
//   scaler: [32,4096] f32
//   out: [2048,4096] f32
//
// Established: sm_103a SIMT HMMA.16816.F32 rt~12/SMSP => GEMM pipe floor
// ~180us; R7 GEMM (BM128xBN128, occ2) is at the floor. R9: merge the two
// DRAM-bound prepasses into ONE kernel (concurrent, one less launch).
// GEMM is bit-identical to the verified R7 kernel.
// ============================================================================

static constexpr int M = 2048;
static constexpr int N = 4096;
static constexpr int K = 4096;

static constexpr int BM = 128;
static constexpr int BN = 128;
static constexpr int BK = 64;            // 64 halves = 128 bytes per row
static constexpr int STAGES = 3;
static constexpr int KITERS = K / BK;    // 64

static constexpr int A_BYTES = BM * BK * 2;              // 16384
static constexpr int B_BYTES = BN * BK * 2;              // 16384
static constexpr int STAGE_BYTES = A_BYTES + B_BYTES;    // 32768
static constexpr int SMEM_TOTAL = STAGES * STAGE_BYTES;  // 98304 (x2 CTAs/SM)

// Scratch (static device globals -- allocation-free)
__device__ __half g_x16[(size_t)M * K];   // 16 MB : x fp16, [M][K]
__device__ __half g_wt [(size_t)N * K];   // 32 MB : dequant W^T fp16, [N][K]

// ---------------------------------------------------------------------------
__device__ __forceinline__ uint32_t smem_u32(const void* p) {
    uint32_t a;
    asm("{ .reg .u64 t; cvta.to.shared.u64 t, %1; cvt.u32.u64 %0, t; }"
        : "=r"(a) : "l"(p));
    return a;
}
__device__ __forceinline__ void cp_async_16(uint32_t dst, const void* src) {
    asm volatile("cp.async.cg.shared.global [%0], [%1], 16;"
                 :: "r"(dst), "l"(src) : "memory");
}
__device__ __forceinline__ void cp_commit() {
    asm volatile("cp.async.commit_group;" ::: "memory");
}
__device__ __forceinline__ void cp_wait1() {
    asm volatile("cp.async.wait_group 1;" ::: "memory");
}
__device__ __forceinline__ void ldsm_x4(uint32_t* r, uint32_t addr) {
    asm volatile("ldmatrix.sync.aligned.m8n8.x4.shared.b16 {%0,%1,%2,%3}, [%4];"
                 : "=r"(r[0]), "=r"(r[1]), "=r"(r[2]), "=r"(r[3]) : "r"(addr));
}
__device__ __forceinline__ void mma16816(float* c, const uint32_t* a,
                                         uint32_t b0, uint32_t b1) {
    asm volatile(
        "mma.sync.aligned.m16n8k16.row.col.f32.f16.f16.f32 "
        "{%0,%1,%2,%3}, {%4,%5,%6,%7}, {%8,%9}, {%0,%1,%2,%3};"
        : "+f"(c[0]), "+f"(c[1]), "+f"(c[2]), "+f"(c[3])
        : "r"(a[0]), "r"(a[1]), "r"(a[2]), "r"(a[3]), "r"(b0), "r"(b1));
}

// ============================================================================
// Kernel 1: merged prepass.
//   blocks [0, 1024):    dequant + transpose W -> Wt[n][k] fp16
//   blocks [1024, 5120): x fp32 -> fp16 (8 floats / thread)
// Both DRAM-bound; running them in one grid overlaps their memory traffic.
// ============================================================================
__global__ void __launch_bounds__(256) prep_kernel(const float4* __restrict__ x,
                                                   uint4* __restrict__ xo,
                                                   const int* __restrict__ w,
                                                   const float* __restrict__ sc,
                                                   __half* __restrict__ wt) {
    __shared__ __half tile[128][130];
    const int bid = blockIdx.x;
    const int tid = threadIdx.x;

    if (bid >= 1024) {
        // ---- convert_x part (verified R5 logic) ----
        size_t i = (size_t)(bid - 1024) * 256 + tid;
        float4 a = x[2 * i];
        float4 b = x[2 * i + 1];
        __half2 h0 = __floats2half2_rn(a.x, a.y);
        __half2 h1 = __floats2half2_rn(a.z, a.w);
        __half2 h2 = __floats2half2_rn(b.x, b.y);
        __half2 h3 = __floats2half2_rn(b.z, b.w);
        uint4 v;
        v.x = reinterpret_cast<uint32_t&>(h0);
        v.y = reinterpret_cast<uint32_t&>(h1);
        v.z = reinterpret_cast<uint32_t&>(h2);
        v.w = reinterpret_cast<uint32_t&>(h3);
        xo[i] = v;
        return;
    }

    // ---- dequant part (verified R5 logic; int32 weights) ----
    const int s  = bid >> 5;             // 0..31
    const int n0 = (bid & 31) * 128;

    #pragma unroll
    for (int i = tid; i < 128 * 32; i += 256) {
        int c = i >> 5;
        int n = (i & 31) * 4;
        const int4   q = *(const int4*)(w + ((size_t)(s * 128 + c)) * 4096 + n0 + n);
        const float4 f = *(const float4*)(sc + (size_t)s * 4096 + n0 + n);
        __half2 h0 = __floats2half2_rn((float)q.x * f.x, (float)q.y * f.y);
        __half2 h1 = __floats2half2_rn((float)q.z * f.z, (float)q.w * f.w);
        *(__half2*)&tile[c][n]     = h0;
        *(__half2*)&tile[c][n + 2] = h1;
    }
    __syncthreads();

    #pragma unroll
    for (int i = tid; i < 128 * 32; i += 256) {
        int cq = i & 31;
        int n  = i >> 5;
        int c0 = cq * 4;
        uint32_t lo = (uint32_t)__half_as_ushort(tile[c0 + 0][n]) |
                      ((uint32_t)__half_as_ushort(tile[c0 + 1][n]) << 16);
        uint32_t hi = (uint32_t)__half_as_ushort(tile[c0 + 2][n]) |
                      ((uint32_t)__half_as_ushort(tile[c0 + 3][n]) << 16);
        uint2 v; v.x = lo; v.y = hi;
        *(uint2*)(wt + (size_t)(n0 + n) * 4096 + s * 128 + c0) = v;
    }
}

// ============================================================================
// Kernel 2: fp16 HMMA GEMM  [bit-identical to verified R7 kernel]
//   BM=128 x BN=128 x BK=64, 256 threads (8 warps: 2m x 4n, warp 64m x 32n),
//   3-stage cp.async ring, one __syncthreads per iter, 2 CTAs/SM.
// ============================================================================
__global__ void __launch_bounds__(256, 2)
gemm_kernel(const __half* __restrict__ A, const __half* __restrict__ B,
            float* __restrict__ out) {
    extern __shared__ char smem[];
    const uint32_t sb = smem_u32(smem);

    const int tid  = threadIdx.x;
    const int wid  = tid >> 5;
    const int lane = tid & 31;

    const int mt = blockIdx.x & 15;      // 16 m-tiles
    const int nt = blockIdx.x >> 4;      // 32 n-tiles
    const int m0 = mt * BM;
    const int n0 = nt * BN;

    const int wm = (wid & 1) * 64;       // 2 warps over m
    const int wn = (wid >> 1) * 32;      // 4 warps over n

    // ---- cp.async bases ----
    const int row0 = tid >> 3;           // 0..31
    const int cc   = tid & 7;
    const uint32_t dst0 = (uint32_t)row0 * 128 + (((cc ^ (row0 & 7)) << 4));
    const __half* a_base = A + (size_t)(m0 + row0) * K + cc * 8;
    const __half* b_base = B + (size_t)(n0 + row0) * K + cc * 8;

    // ---- ldmatrix lane addressing (verified mapping) ----
    int a_row[4];
    #pragma unroll
    for (int mi = 0; mi < 4; ++mi) a_row[mi] = wm + mi * 16 + (lane & 15);
    const int a_hi = lane >> 4;
    const int b_hi = (lane >> 3) & 1;
    int b_row[2];
    #pragma unroll
    for (int nb = 0; nb < 2; ++nb)
        b_row[nb] = wn + nb * 16 + (lane & 7) + 8 * (lane >> 4);

    float acc[4][4][4];
    #pragma unroll
    for (int mi = 0; mi < 4; ++mi)
        #pragma unroll
        for (int ni = 0; ni < 4; ++ni)
            #pragma unroll
            for (int j = 0; j < 4; ++j) acc[mi][ni][j] = 0.f;

    auto load_stage = [&](int it, int stage) {
        uint32_t sd = sb + stage * STAGE_BYTES;
        size_t koff = (size_t)it * BK;
        #pragma unroll
        for (int i = 0; i < 4; ++i)       // A rows row0 + 32i
            cp_async_16(sd + dst0 + i * (32 * 128), a_base + koff + (size_t)(32 * i) * K);
        #pragma unroll
        for (int i = 0; i < 4; ++i)       // B rows row0 + 32i
            cp_async_16(sd + A_BYTES + dst0 + i * (32 * 128),
                        b_base + koff + (size_t)(32 * i) * K);
    };

    load_stage(0, 0); cp_commit();
    load_stage(1, 1); cp_commit();

    int stage_w = 2;                      // next write slot
    #pragma unroll 1
    for (int it = 0; it < KITERS; ++it) {
        cp_wait1();                       // stage it resident (only it+1 pending)
        __syncthreads();                  // everyone done reading stage it-1

        if (it + 2 < KITERS) load_stage(it + 2, stage_w);
        cp_commit();
        stage_w = (stage_w == 2) ? 0 : stage_w + 1;

        const uint32_t sA = sb + (it % STAGES) * STAGE_BYTES;
        const uint32_t sB = sA + A_BYTES;

        #pragma unroll
        for (int ks = 0; ks < 4; ++ks) {
            uint32_t a_frag[4][4], b_frag[2][4];
            #pragma unroll
            for (int mi = 0; mi < 4; ++mi) {
                uint32_t c = (uint32_t)((ks * 2 + a_hi) ^ (a_row[mi] & 7)) << 4;
                ldsm_x4(a_frag[mi], sA + a_row[mi] * 128 + c);
            }
            #pragma unroll
            for (int nb = 0; nb < 2; ++nb) {
                uint32_t c = (uint32_t)((ks * 2 + b_hi) ^ (b_row[nb] & 7)) << 4;
                ldsm_x4(b_frag[nb], sB + b_row[nb] * 128 + c);
            }
            #pragma unroll
            for (int mi = 0; mi < 4; ++mi)
                #pragma unroll
                for (int nb = 0; nb < 2; ++nb) {
                    mma16816(acc[mi][2 * nb + 0], a_frag[mi], b_frag[nb][0], b_frag[nb][1]);
                    mma16816(acc[mi][2 * nb + 1], a_frag[mi], b_frag[nb][2], b_frag[nb][3]);
                }
        }
    }

    // ---- epilogue (verified c-fragment mapping) ----
    const int r0 = m0 + wm + (lane >> 2);
    const int c0 = n0 + wn + (lane & 3) * 2;
    #pragma unroll
    for (int mi = 0; mi < 4; ++mi) {
        #pragma unroll
        for (int ni = 0; ni < 4; ++ni) {
            int r = r0 + mi * 16;
            int c = c0 + ni * 8;
            *(float2*)(out + (size_t)r * N + c)       = make_float2(acc[mi][ni][0], acc[mi][ni][1]);
            *(float2*)(out + (size_t)(r + 8) * N + c) = make_float2(acc[mi][ni][2], acc[mi][ni][3]);
        }
    }
}

// ============================================================================
// Host launch
// ============================================================================
extern "C" void kernel_launch(void* const* d_in, const int* in_sizes, int n_in,
                              void* d_out, int out_size) {
    const float* x  = (const float*)d_in[0];
    const int*   w  = (const int*)d_in[1];     // int8 promoted to int32 by harness
    const float* sc = (const float*)d_in[2];
    float* out = (float*)d_out;

    void* p_x16 = nullptr;
    void* p_wt  = nullptr;
    cudaGetSymbolAddress(&p_x16, g_x16);
    cudaGetSymbolAddress(&p_wt,  g_wt);

    // merged prepass: 1024 dequant blocks + 4096 convert blocks
    prep_kernel<<<1024 + 4096, 256>>>((const float4*)x, (uint4*)p_x16,
                                      w, sc, (__half*)p_wt);

    cudaFuncSetAttribute(gemm_kernel, cudaFuncAttributeMaxDynamicSharedMemorySize,
                         SMEM_TOTAL);
    gemm_kernel<<<(M / BM) * (N / BN), 256, SMEM_TOTAL>>>(
        (const __half*)p_x16, (const __half*)p_wt, out);
}